// round 4
// baseline (speedup 1.0000x reference)
#include <cuda_runtime.h>
#include <cstdint>
#include <cstdio>

// ---------------- problem constants ----------------
#define SD    128
#define AD    32
#define KDIM  160     // SD + AD
#define HDIM  256
#define NQ    4
#define NL    2
#define BM    128     // batch rows per CTA
#define LDA   172     // smem row stride (floats): conflict-free fragment loads
#define NCHUNK 64     // h-columns per chunk
#define NCHUNKS 8     // 2 branches * (256/64)
#define EPSZ  320     // per-chunk epilogue pack: b1 (64) + W2 (4*64)

// Precomputed observable matrices: A[br] = pw * Re(U^H Z0 U), plus pb
__device__ float g_A[2][16][16];
__device__ float g_pb[2];
// Pre-packed W1 in exact smem image (tf32 bits, kperm-permuted, LDA-strided)
__device__ __align__(16) uint32_t g_Wpack[2][HDIM][LDA];
// Per-chunk epilogue pack: [0:64) b1, [64:320) W2 (q-major)
__device__ __align__(16) float g_EPack[NCHUNKS][EPSZ];

// ---------------- complex helpers ----------------
__device__ __forceinline__ float2 cmul(float2 a, float2 b) {
    return make_float2(a.x * b.x - a.y * b.y, a.x * b.y + a.y * b.x);
}
__device__ __forceinline__ float2 cadd(float2 a, float2 b) {
    return make_float2(a.x + b.x, a.y + b.y);
}

template <int M>
__device__ __forceinline__ void apply1q(float2* v, float2 g00, float2 g01,
                                        float2 g10, float2 g11) {
#pragma unroll
    for (int k = 0; k < 16; k++) {
        if (!(k & M)) {
            float2 a = v[k], b = v[k | M];
            v[k]     = cadd(cmul(g00, a), cmul(g01, b));
            v[k | M] = cadd(cmul(g10, a), cmul(g11, b));
        }
    }
}

template <int MC, int MT>
__device__ __forceinline__ void cnot(float2* v) {
#pragma unroll
    for (int k = 0; k < 16; k++) {
        if ((k & MC) && !(k & MT)) {
            float2 tmp = v[k]; v[k] = v[k | MT]; v[k | MT] = tmp;
        }
    }
}

// RX, RY, RZ with angles w[0..2] on qubit with bitmask M
template <int M>
__device__ __forceinline__ void rot3(float2* v, const float* w) {
    float c, s;
    sincosf(0.5f * w[0], &s, &c);  // RX: [[c, -is],[-is, c]]
    apply1q<M>(v, make_float2(c, 0.f), make_float2(0.f, -s),
                  make_float2(0.f, -s), make_float2(c, 0.f));
    sincosf(0.5f * w[1], &s, &c);  // RY: [[c, -s],[s, c]]
    apply1q<M>(v, make_float2(c, 0.f), make_float2(-s, 0.f),
                  make_float2(s, 0.f), make_float2(c, 0.f));
    sincosf(0.5f * w[2], &s, &c);  // RZ: diag(e^{-i t/2}, e^{+i t/2})
    apply1q<M>(v, make_float2(c, -s), make_float2(0.f, 0.f),
                  make_float2(0.f, 0.f), make_float2(c, s));
}

// Build 16x16 layer unitary per branch (thread = column), then reduce to
// A[j][i] = pw * sum_k z_k * Re(conj(U[k][j]) * U[k][i]),  z_k = +1 (k<8) else -1.
__global__ void precompute_kernel(const float* __restrict__ qw1, const float* __restrict__ qw2,
                                  const float* __restrict__ pw1, const float* __restrict__ pb1,
                                  const float* __restrict__ pw2, const float* __restrict__ pb2) {
    __shared__ float2 Ush[2][16][16];  // [branch][row k][col]
    int tid = threadIdx.x;  // 64 threads
    if (tid < 32) {
        int br = tid >> 4, col = tid & 15;
        const float* qw = br ? qw2 : qw1;
        float2 v[16];
#pragma unroll
        for (int k = 0; k < 16; k++) v[k] = make_float2(k == col ? 1.f : 0.f, 0.f);
#pragma unroll
        for (int l = 0; l < NL; l++) {
            const float* wl = qw + l * 12;
            rot3<8>(v, wl + 0);   // qubit 0 (MSB)
            rot3<4>(v, wl + 3);   // qubit 1
            rot3<2>(v, wl + 6);   // qubit 2
            rot3<1>(v, wl + 9);   // qubit 3
            cnot<8, 4>(v);        // CNOT(0,1)
            cnot<4, 2>(v);        // CNOT(1,2)
            cnot<2, 1>(v);        // CNOT(2,3)
            cnot<1, 8>(v);        // CNOT(3,0)
        }
#pragma unroll
        for (int k = 0; k < 16; k++) Ush[br][k][col] = v[k];
    }
    __syncthreads();
    for (int e = tid; e < 512; e += 64) {
        int br = e >> 8, j = (e >> 4) & 15, i = e & 15;
        float s = 0.f;
#pragma unroll
        for (int k = 0; k < 16; k++) {
            float2 uj = Ush[br][k][j], ui = Ush[br][k][i];
            float t = uj.x * ui.x + uj.y * ui.y;
            s += (k < 8) ? t : -t;
        }
        float pw = br ? pw2[0] : pw1[0];
        g_A[br][j][i] = pw * s;
    }
    if (tid == 0) { g_pb[0] = pb1[0]; g_pb[1] = pb2[0]; }
}

// k-permutation inside each 8-group so fragment pairs (t, t+4) are contiguous:
// j<4 -> 2j ; j>=4 -> 2(j-4)+1
__device__ __forceinline__ int kperm(int k) {
    return (k & ~7) | (((k & 3) << 1) | ((k >> 2) & 1));
}

// Pack W1 (both branches) into the exact smem image; pack b1/W2 per chunk.
__global__ void pack_kernel(const float* __restrict__ W1a, const float* __restrict__ b1a,
                            const float* __restrict__ W2a,
                            const float* __restrict__ W1b, const float* __restrict__ b1b,
                            const float* __restrict__ W2b) {
    int e = blockIdx.x * blockDim.x + threadIdx.x;
    if (e < 2 * HDIM * KDIM) {
        int br = e / (HDIM * KDIM);
        int rem = e - br * HDIM * KDIM;
        int h = rem / KDIM, k = rem - h * KDIM;
        float v = (br ? W1b : W1a)[h * KDIM + k];
        uint32_t u; asm("cvt.rna.tf32.f32 %0, %1;" : "=r"(u) : "f"(v));
        g_Wpack[br][h][kperm(k)] = u;
        if (k >= KDIM - 12 && kperm(k) < LDA) { /* no-op */ }
    }
    // zero-fill padding columns so cp.async source is deterministic
    if (e < 2 * HDIM * (LDA - KDIM)) {
        int br = e / (HDIM * (LDA - KDIM));
        int rem = e - br * HDIM * (LDA - KDIM);
        int h = rem / (LDA - KDIM), p = rem - h * (LDA - KDIM);
        g_Wpack[br][h][KDIM + p] = 0u;
    }
    if (blockIdx.x == 0) {
        for (int i = threadIdx.x; i < NCHUNKS * EPSZ; i += blockDim.x) {
            int ch = i / EPSZ, j = i - ch * EPSZ;
            int br = ch >> 2, h0 = (ch & 3) * NCHUNK;
            const float* b1 = br ? b1b : b1a;
            const float* W2 = br ? W2b : W2a;
            float v = (j < 64) ? b1[h0 + j]
                               : W2[((j - 64) >> 6) * HDIM + h0 + ((j - 64) & 63)];
            g_EPack[ch][j] = v;
        }
    }
}

// ---------------- fused main kernel ----------------
#define MMA_TF32(d0, d1, d2, d3, a0, a1, a2, a3, b0, b1)                        \
    asm volatile(                                                               \
        "mma.sync.aligned.m16n8k8.row.col.f32.tf32.tf32.f32 "                   \
        "{%0,%1,%2,%3}, {%4,%5,%6,%7}, {%8,%9}, {%0,%1,%2,%3};"                 \
        : "+f"(d0), "+f"(d1), "+f"(d2), "+f"(d3)                                \
        : "r"(a0), "r"(a1), "r"(a2), "r"(a3), "r"(b0), "r"(b1))

__device__ __forceinline__ void cp16(void* dst_smem, const void* src_gmem) {
    uint32_t d = (uint32_t)__cvta_generic_to_shared(dst_smem);
    asm volatile("cp.async.cg.shared.global [%0], [%1], 16;" :: "r"(d), "l"(src_gmem));
}
__device__ __forceinline__ void cp_commit() {
    asm volatile("cp.async.commit_group;");
}
template <int N>
__device__ __forceinline__ void cp_wait() {
    asm volatile("cp.async.wait_group %0;" :: "n"(N));
}

__global__ __launch_bounds__(256, 1)
void fused_kernel(const float* __restrict__ state, const float* __restrict__ action,
                  const float* __restrict__ b2a, const float* __restrict__ b2b,
                  float* __restrict__ out, int B) {
    extern __shared__ float sm[];
    float* Asm  = sm;                          // BM*LDA           (22016 f)
    float* Wsm  = Asm + BM * LDA;              // 2*NCHUNK*LDA     (22016 f)
    float* qsm  = Wsm + 2 * NCHUNK * LDA;      // 2*BM*4           (1024 f)
    float* EPsm = qsm + 2 * BM * 4;            // 2*EPSZ           (640 f)
    float* Ash  = EPsm + 2 * EPSZ;             // 2*16*16          (512 f)
    __shared__ float pbsh[2];

    uint32_t* Asmu = reinterpret_cast<uint32_t*>(Asm);
    uint32_t* Wsmu = reinterpret_cast<uint32_t*>(Wsm);

    const int tid = threadIdx.x;
    const int m0  = blockIdx.x * BM;

    // Issue chunk 0 W pack copy immediately (flies during A staging)
    {
        const float4* src = reinterpret_cast<const float4*>(&g_Wpack[0][0][0]);
        float4* dst = reinterpret_cast<float4*>(Wsm);
        for (int i = tid; i < NCHUNK * LDA / 4; i += 256) cp16(dst + i, src + i);
        if (tid < EPSZ / 4)
            cp16(reinterpret_cast<float4*>(EPsm) + tid,
                 reinterpret_cast<const float4*>(&g_EPack[0][0]) + tid);
        cp_commit();
    }

    // Stage A tile [128 x 160] (tf32, k-permuted)
    for (int idx = tid; idx < BM * KDIM; idx += 256) {
        int r = idx / KDIM, k = idx - r * KDIM;
        float v = (k < SD) ? state[(size_t)(m0 + r) * SD + k]
                           : action[(size_t)(m0 + r) * AD + (k - SD)];
        uint32_t u; asm("cvt.rna.tf32.f32 %0, %1;" : "=r"(u) : "f"(v));
        Asmu[r * LDA + kperm(k)] = u;
    }
    // qin accumulators initialized with b2
    for (int e = tid; e < 2 * BM * 4; e += 256) {
        int br = e >> 9, q = e & 3;
        qsm[e] = br ? b2b[q] : b2a[q];
    }
    for (int e = tid; e < 512; e += 256) Ash[e] = (&g_A[0][0][0])[e];
    if (tid < 2) pbsh[tid] = g_pb[tid];

    const int warp = tid >> 5, lane = tid & 31;
    const int g = lane >> 2, t = lane & 3;
    const int mrow0 = (warp & 3) * 32;   // 4 m-warps
    const int ncol0 = (warp >> 2) * 32;  // 2 n-warps

    for (int ch = 0; ch < NCHUNKS; ch++) {
        const int bufi = ch & 1;
        // barrier 1: all warps done reading the buffer chunk ch+1 will overwrite
        // (also orders A-tile/qsm/Ash stores on first iteration)
        __syncthreads();
        if (ch + 1 < NCHUNKS) {
            const int nch = ch + 1, nbuf = nch & 1;
            const float4* src = reinterpret_cast<const float4*>(
                &g_Wpack[nch >> 2][(nch & 3) * NCHUNK][0]);
            float4* dst = reinterpret_cast<float4*>(Wsm + nbuf * (NCHUNK * LDA));
            for (int i = tid; i < NCHUNK * LDA / 4; i += 256) cp16(dst + i, src + i);
            if (tid < EPSZ / 4)
                cp16(reinterpret_cast<float4*>(EPsm + nbuf * EPSZ) + tid,
                     reinterpret_cast<const float4*>(&g_EPack[nch][0]) + tid);
            cp_commit();
            cp_wait<1>();   // chunk ch complete (ch+1 still in flight)
        } else {
            cp_wait<0>();
        }
        // barrier 2: chunk ch data visible to all warps
        __syncthreads();

        const int br = ch >> 2;
        const uint32_t* Wb = Wsmu + bufi * (NCHUNK * LDA);
        const float* b1sm = EPsm + bufi * EPSZ;
        const float* W2sm = b1sm + 64;

        float acc[2][4][4];
#pragma unroll
        for (int mi = 0; mi < 2; mi++)
#pragma unroll
            for (int ni = 0; ni < 4; ni++)
#pragma unroll
                for (int r4 = 0; r4 < 4; r4++) acc[mi][ni][r4] = 0.f;

#pragma unroll
        for (int kk = 0; kk < KDIM; kk += 8) {
            uint32_t a[2][4];
#pragma unroll
            for (int mi = 0; mi < 2; mi++) {
                uint2 lo = *reinterpret_cast<const uint2*>(
                    &Asmu[(mrow0 + mi * 16 + g) * LDA + kk + 2 * t]);
                uint2 hi = *reinterpret_cast<const uint2*>(
                    &Asmu[(mrow0 + mi * 16 + 8 + g) * LDA + kk + 2 * t]);
                a[mi][0] = lo.x; a[mi][1] = hi.x; a[mi][2] = lo.y; a[mi][3] = hi.y;
            }
#pragma unroll
            for (int ni = 0; ni < 4; ni++) {
                uint2 bb = *reinterpret_cast<const uint2*>(
                    &Wb[(ncol0 + ni * 8 + g) * LDA + kk + 2 * t]);
#pragma unroll
                for (int mi = 0; mi < 2; mi++) {
                    MMA_TF32(acc[mi][ni][0], acc[mi][ni][1], acc[mi][ni][2], acc[mi][ni][3],
                             a[mi][0], a[mi][1], a[mi][2], a[mi][3], bb.x, bb.y);
                }
            }
        }

        // epilogue: bias + relu + partial qin = h @ W2^T for this chunk
        float hb[8], w2r[4][8];
#pragma unroll
        for (int ni = 0; ni < 4; ni++)
#pragma unroll
            for (int j = 0; j < 2; j++) {
                int col = ncol0 + ni * 8 + 2 * t + j;
                hb[ni * 2 + j] = b1sm[col];
#pragma unroll
                for (int q = 0; q < 4; q++) w2r[q][ni * 2 + j] = W2sm[q * 64 + col];
            }
#pragma unroll
        for (int mi = 0; mi < 2; mi++)
#pragma unroll
            for (int half = 0; half < 2; half++) {
                int rrow = mrow0 + mi * 16 + half * 8 + g;
                float p[4] = {0.f, 0.f, 0.f, 0.f};
#pragma unroll
                for (int ni = 0; ni < 4; ni++)
#pragma unroll
                    for (int j = 0; j < 2; j++) {
                        float h = acc[mi][ni][half * 2 + j] + hb[ni * 2 + j];
                        h = fmaxf(h, 0.f);
#pragma unroll
                        for (int q = 0; q < 4; q++) p[q] += h * w2r[q][ni * 2 + j];
                    }
#pragma unroll
                for (int q = 0; q < 4; q++) {
                    p[q] += __shfl_xor_sync(0xffffffffu, p[q], 1);
                    p[q] += __shfl_xor_sync(0xffffffffu, p[q], 2);
                }
                if (t == 0) {
#pragma unroll
                    for (int q = 0; q < 4; q++)
                        atomicAdd(&qsm[(br * BM + rrow) * 4 + q], p[q]);
                }
            }
    }
    __syncthreads();

    // finalize: circuit expval via quadratic form + output affine
    {
        const int r = tid & 127, br = tid >> 7;
        float qv[4];
#pragma unroll
        for (int q = 0; q < 4; q++) qv[q] = qsm[(br * BM + r) * 4 + q];
        float cc[4], ss[4];
#pragma unroll
        for (int q = 0; q < 4; q++) sincosf(0.5f * qv[q], &ss[q], &cc[q]);
        float phi[16];
#pragma unroll
        for (int k = 0; k < 16; k++) {
            float v = (k & 8) ? ss[0] : cc[0];
            v *= (k & 4) ? ss[1] : cc[1];
            v *= (k & 2) ? ss[2] : cc[2];
            v *= (k & 1) ? ss[3] : cc[3];
            phi[k] = v;
        }
        const float* Am = Ash + br * 256;
        float e = 0.f;
#pragma unroll
        for (int j = 0; j < 16; j++) {
            float rs = 0.f;
#pragma unroll
            for (int i = 0; i < 16; i++) rs += Am[j * 16 + i] * phi[i];
            e += phi[j] * rs;
        }
        out[(size_t)br * B + m0 + r] = e + pbsh[br];
    }
}

// ---------------- launch ----------------
#define SMEM_FLOATS (BM * LDA + 2 * NCHUNK * LDA + 2 * BM * 4 + 2 * EPSZ + 512)
#define SMEM_BYTES  (SMEM_FLOATS * 4)

extern "C" void kernel_launch(void* const* d_in, const int* in_sizes, int n_in,
                              void* d_out, int out_size) {
    (void)n_in; (void)out_size;
    const float* state = (const float*)d_in[0];
    const float* action = (const float*)d_in[1];
    const float* q1_W1 = (const float*)d_in[2];
    const float* q1_b1 = (const float*)d_in[3];
    const float* q1_W2 = (const float*)d_in[4];
    const float* q1_b2 = (const float*)d_in[5];
    const float* q2_W1 = (const float*)d_in[6];
    const float* q2_b1 = (const float*)d_in[7];
    const float* q2_W2 = (const float*)d_in[8];
    const float* q2_b2 = (const float*)d_in[9];
    const float* q1_qw = (const float*)d_in[10];
    const float* q2_qw = (const float*)d_in[11];
    const float* q1_pw = (const float*)d_in[12];
    const float* q1_pb = (const float*)d_in[13];
    const float* q2_pw = (const float*)d_in[14];
    const float* q2_pb = (const float*)d_in[15];
    float* out = (float*)d_out;

    int B = in_sizes[0] / SD;

    cudaFuncSetAttribute(fused_kernel, cudaFuncAttributeMaxDynamicSharedMemorySize,
                         SMEM_BYTES);

    precompute_kernel<<<1, 64>>>(q1_qw, q2_qw, q1_pw, q1_pb, q2_pw, q2_pb);
    pack_kernel<<<(2 * HDIM * KDIM + 255) / 256, 256>>>(q1_W1, q1_b1, q1_W2,
                                                        q2_W1, q2_b1, q2_W2);
    fused_kernel<<<B / BM, 256, SMEM_BYTES>>>(state, action, q1_b2, q2_b2, out, B);
}

// round 9
// speedup vs baseline: 1.2042x; 1.2042x over previous
#include <cuda_runtime.h>
#include <cstdint>
#include <cstdio>

// ---------------- problem constants ----------------
#define SD    128
#define AD    32
#define KDIM  160     // SD + AD
#define HDIM  256
#define NQ    4
#define NL    2
#define BM    128     // batch rows per CTA
#define LDA   168     // smem row stride (floats); 168 % 32 == 8 -> conflict-free frags
#define NCHUNK 64     // h-columns per chunk
#define NCHUNKS 8     // 2 branches * (256/64)
#define EPSZ  320     // per-chunk epilogue pack: b1 (64) + W2 (4*64)

// Precomputed observable matrices: A[br] = pw * Re(U^H Z0 U), plus pb
__device__ float g_A[2][16][16];
__device__ float g_pb[2];
// Pre-packed W1 in exact smem image (tf32 bits, kperm-permuted, LDA-strided)
__device__ __align__(16) uint32_t g_Wpack[2][HDIM][LDA];
// Per-chunk epilogue pack: [0:64) b1, [64:320) W2 (q-major)
__device__ __align__(16) float g_EPack[NCHUNKS][EPSZ];

// ---------------- complex helpers ----------------
__device__ __forceinline__ float2 cmul(float2 a, float2 b) {
    return make_float2(a.x * b.x - a.y * b.y, a.x * b.y + a.y * b.x);
}
__device__ __forceinline__ float2 cadd(float2 a, float2 b) {
    return make_float2(a.x + b.x, a.y + b.y);
}

template <int M>
__device__ __forceinline__ void apply1q(float2* v, float2 g00, float2 g01,
                                        float2 g10, float2 g11) {
#pragma unroll
    for (int k = 0; k < 16; k++) {
        if (!(k & M)) {
            float2 a = v[k], b = v[k | M];
            v[k]     = cadd(cmul(g00, a), cmul(g01, b));
            v[k | M] = cadd(cmul(g10, a), cmul(g11, b));
        }
    }
}

template <int MC, int MT>
__device__ __forceinline__ void cnot(float2* v) {
#pragma unroll
    for (int k = 0; k < 16; k++) {
        if ((k & MC) && !(k & MT)) {
            float2 tmp = v[k]; v[k] = v[k | MT]; v[k | MT] = tmp;
        }
    }
}

// RX, RY, RZ with angles w[0..2] on qubit with bitmask M
template <int M>
__device__ __forceinline__ void rot3(float2* v, const float* w) {
    float c, s;
    sincosf(0.5f * w[0], &s, &c);  // RX
    apply1q<M>(v, make_float2(c, 0.f), make_float2(0.f, -s),
                  make_float2(0.f, -s), make_float2(c, 0.f));
    sincosf(0.5f * w[1], &s, &c);  // RY
    apply1q<M>(v, make_float2(c, 0.f), make_float2(-s, 0.f),
                  make_float2(s, 0.f), make_float2(c, 0.f));
    sincosf(0.5f * w[2], &s, &c);  // RZ
    apply1q<M>(v, make_float2(c, -s), make_float2(0.f, 0.f),
                  make_float2(0.f, 0.f), make_float2(c, s));
}

// k-permutation inside each 8-group so fragment pairs (t, t+4) are contiguous:
// j<4 -> 2j ; j>=4 -> 2(j-4)+1
__device__ __forceinline__ int kperm(int k) {
    return (k & ~7) | (((k & 3) << 1) | ((k >> 2) & 1));
}

// Merged prep: W pack (most blocks) + epilogue pack (block 0) + circuit
// precompute (last block). All independent; run concurrently.
__global__ void prep_kernel(const float* __restrict__ W1a, const float* __restrict__ b1a,
                            const float* __restrict__ W2a,
                            const float* __restrict__ W1b, const float* __restrict__ b1b,
                            const float* __restrict__ W2b,
                            const float* __restrict__ qw1, const float* __restrict__ qw2,
                            const float* __restrict__ pw1, const float* __restrict__ pb1,
                            const float* __restrict__ pw2, const float* __restrict__ pb2) {
    if (blockIdx.x == gridDim.x - 1) {
        // ---- circuit precompute: A[br] = pw * Re(U^H Z0 U) ----
        __shared__ float2 Ush[2][16][16];  // [branch][row k][col]
        int tid = threadIdx.x;
        if (tid < 32) {
            int br = tid >> 4, col = tid & 15;
            const float* qw = br ? qw2 : qw1;
            float2 v[16];
#pragma unroll
            for (int k = 0; k < 16; k++) v[k] = make_float2(k == col ? 1.f : 0.f, 0.f);
#pragma unroll
            for (int l = 0; l < NL; l++) {
                const float* wl = qw + l * 12;
                rot3<8>(v, wl + 0);   // qubit 0 (MSB)
                rot3<4>(v, wl + 3);   // qubit 1
                rot3<2>(v, wl + 6);   // qubit 2
                rot3<1>(v, wl + 9);   // qubit 3
                cnot<8, 4>(v);        // CNOT(0,1)
                cnot<4, 2>(v);        // CNOT(1,2)
                cnot<2, 1>(v);        // CNOT(2,3)
                cnot<1, 8>(v);        // CNOT(3,0)
            }
#pragma unroll
            for (int k = 0; k < 16; k++) Ush[br][k][col] = v[k];
        }
        __syncthreads();
        for (int e = tid; e < 512; e += blockDim.x) {
            int br = e >> 8, j = (e >> 4) & 15, i = e & 15;
            float s = 0.f;
#pragma unroll
            for (int k = 0; k < 16; k++) {
                float2 uj = Ush[br][k][j], ui = Ush[br][k][i];
                float t = uj.x * ui.x + uj.y * ui.y;
                s += (k < 8) ? t : -t;
            }
            float pw = br ? pw2[0] : pw1[0];
            g_A[br][j][i] = pw * s;
        }
        if (tid == 0) { g_pb[0] = pb1[0]; g_pb[1] = pb2[0]; }
        return;
    }

    // ---- W1 pack (tf32 bits, kperm, LDA-strided smem image) ----
    int e = blockIdx.x * blockDim.x + threadIdx.x;
    if (e < 2 * HDIM * KDIM) {
        int br = e / (HDIM * KDIM);
        int rem = e - br * HDIM * KDIM;
        int h = rem / KDIM, k = rem - h * KDIM;
        float v = (br ? W1b : W1a)[h * KDIM + k];
        uint32_t u; asm("cvt.rna.tf32.f32 %0, %1;" : "=r"(u) : "f"(v));
        g_Wpack[br][h][kperm(k)] = u;
    }
    // zero-fill padding columns so cp.async source is deterministic
    if (e < 2 * HDIM * (LDA - KDIM)) {
        int br = e / (HDIM * (LDA - KDIM));
        int rem = e - br * HDIM * (LDA - KDIM);
        int h = rem / (LDA - KDIM), p = rem - h * (LDA - KDIM);
        g_Wpack[br][h][KDIM + p] = 0u;
    }
    if (blockIdx.x == 0) {
        for (int i = threadIdx.x; i < NCHUNKS * EPSZ; i += blockDim.x) {
            int ch = i / EPSZ, j = i - ch * EPSZ;
            int br = ch >> 2, h0 = (ch & 3) * NCHUNK;
            const float* b1 = br ? b1b : b1a;
            const float* W2 = br ? W2b : W2a;
            float v = (j < 64) ? b1[h0 + j]
                               : W2[((j - 64) >> 6) * HDIM + h0 + ((j - 64) & 63)];
            g_EPack[ch][j] = v;
        }
    }
}

// ---------------- fused main kernel ----------------
#define MMA_TF32(d0, d1, d2, d3, a0, a1, a2, a3, b0, b1)                        \
    asm volatile(                                                               \
        "mma.sync.aligned.m16n8k8.row.col.f32.tf32.tf32.f32 "                   \
        "{%0,%1,%2,%3}, {%4,%5,%6,%7}, {%8,%9}, {%0,%1,%2,%3};"                 \
        : "+f"(d0), "+f"(d1), "+f"(d2), "+f"(d3)                                \
        : "r"(a0), "r"(a1), "r"(a2), "r"(a3), "r"(b0), "r"(b1))

__device__ __forceinline__ void cp16(void* dst_smem, const void* src_gmem) {
    uint32_t d = (uint32_t)__cvta_generic_to_shared(dst_smem);
    asm volatile("cp.async.cg.shared.global [%0], [%1], 16;" :: "r"(d), "l"(src_gmem));
}
__device__ __forceinline__ void cp_commit() {
    asm volatile("cp.async.commit_group;");
}
template <int N>
__device__ __forceinline__ void cp_wait() {
    asm volatile("cp.async.wait_group %0;" :: "n"(N));
}

__global__ __launch_bounds__(256, 1)
void fused_kernel(const float* __restrict__ state, const float* __restrict__ action,
                  const float* __restrict__ b2a, const float* __restrict__ b2b,
                  float* __restrict__ out, int B) {
    extern __shared__ float sm[];
    float* Asm  = sm;                          // BM*LDA           (21504 f)
    float* Wsm  = Asm + BM * LDA;              // 2*NCHUNK*LDA     (21504 f)
    float* qsm  = Wsm + 2 * NCHUNK * LDA;      // 2*BM*4           (1024 f)
    float* EPsm = qsm + 2 * BM * 4;            // 2*EPSZ           (640 f)
    float* Ash  = EPsm + 2 * EPSZ;             // 2*16*16          (512 f)
    __shared__ float pbsh[2];

    uint32_t* Asmu = reinterpret_cast<uint32_t*>(Asm);
    uint32_t* Wsmu = reinterpret_cast<uint32_t*>(Wsm);

    const int tid = threadIdx.x;
    const int m0  = blockIdx.x * BM;

    // Issue chunk 0 W pack copy immediately (flies during A staging)
    {
        const float4* src = reinterpret_cast<const float4*>(&g_Wpack[0][0][0]);
        float4* dst = reinterpret_cast<float4*>(Wsm);
        for (int i = tid; i < NCHUNK * LDA / 4; i += 256) cp16(dst + i, src + i);
        if (tid < EPSZ / 4)
            cp16(reinterpret_cast<float4*>(EPsm) + tid,
                 reinterpret_cast<const float4*>(&g_EPack[0][0]) + tid);
        cp_commit();
    }

    // Stage A tile [128 x 160] (tf32, k-permuted)
    for (int idx = tid; idx < BM * KDIM; idx += 256) {
        int r = idx / KDIM, k = idx - r * KDIM;
        float v = (k < SD) ? state[(size_t)(m0 + r) * SD + k]
                           : action[(size_t)(m0 + r) * AD + (k - SD)];
        uint32_t u; asm("cvt.rna.tf32.f32 %0, %1;" : "=r"(u) : "f"(v));
        Asmu[r * LDA + kperm(k)] = u;
    }
    // qin accumulators initialized with b2
    for (int e = tid; e < 2 * BM * 4; e += 256) {
        int br = e >> 9, q = e & 3;
        qsm[e] = br ? b2b[q] : b2a[q];
    }
    for (int e = tid; e < 512; e += 256) Ash[e] = (&g_A[0][0][0])[e];
    if (tid < 2) pbsh[tid] = g_pb[tid];

    const int warp = tid >> 5, lane = tid & 31;
    const int g = lane >> 2, t = lane & 3;
    const int mrow0 = (warp & 3) * 32;   // 4 m-warps
    const int ncol0 = (warp >> 2) * 32;  // 2 n-warps

    for (int ch = 0; ch < NCHUNKS; ch++) {
        const int bufi = ch & 1;
        // barrier 1: all warps done reading the buffer chunk ch+1 will overwrite
        // (also orders A-tile/qsm/Ash stores on first iteration)
        __syncthreads();
        if (ch + 1 < NCHUNKS) {
            const int nch = ch + 1, nbuf = nch & 1;
            const float4* src = reinterpret_cast<const float4*>(
                &g_Wpack[nch >> 2][(nch & 3) * NCHUNK][0]);
            float4* dst = reinterpret_cast<float4*>(Wsm + nbuf * (NCHUNK * LDA));
            for (int i = tid; i < NCHUNK * LDA / 4; i += 256) cp16(dst + i, src + i);
            if (tid < EPSZ / 4)
                cp16(reinterpret_cast<float4*>(EPsm + nbuf * EPSZ) + tid,
                     reinterpret_cast<const float4*>(&g_EPack[nch][0]) + tid);
            cp_commit();
            cp_wait<1>();   // chunk ch complete (ch+1 still in flight)
        } else {
            cp_wait<0>();
        }
        // barrier 2: chunk ch data visible to all warps
        __syncthreads();

        const int br = ch >> 2;
        const uint32_t* Wb = Wsmu + bufi * (NCHUNK * LDA);
        const float* b1sm = EPsm + bufi * EPSZ;
        const float* W2sm = b1sm + 64;

        float acc[2][4][4];
#pragma unroll
        for (int mi = 0; mi < 2; mi++)
#pragma unroll
            for (int ni = 0; ni < 4; ni++)
#pragma unroll
                for (int r4 = 0; r4 < 4; r4++) acc[mi][ni][r4] = 0.f;

#pragma unroll
        for (int kk = 0; kk < KDIM; kk += 8) {
            uint32_t a[2][4];
#pragma unroll
            for (int mi = 0; mi < 2; mi++) {
                uint2 lo = *reinterpret_cast<const uint2*>(
                    &Asmu[(mrow0 + mi * 16 + g) * LDA + kk + 2 * t]);
                uint2 hi = *reinterpret_cast<const uint2*>(
                    &Asmu[(mrow0 + mi * 16 + 8 + g) * LDA + kk + 2 * t]);
                a[mi][0] = lo.x; a[mi][1] = hi.x; a[mi][2] = lo.y; a[mi][3] = hi.y;
            }
#pragma unroll
            for (int ni = 0; ni < 4; ni++) {
                uint2 bb = *reinterpret_cast<const uint2*>(
                    &Wb[(ncol0 + ni * 8 + g) * LDA + kk + 2 * t]);
#pragma unroll
                for (int mi = 0; mi < 2; mi++) {
                    MMA_TF32(acc[mi][ni][0], acc[mi][ni][1], acc[mi][ni][2], acc[mi][ni][3],
                             a[mi][0], a[mi][1], a[mi][2], a[mi][3], bb.x, bb.y);
                }
            }
        }

        // epilogue: bias + relu + partial qin = h @ W2^T for this chunk
        float hb[8], w2r[4][8];
#pragma unroll
        for (int ni = 0; ni < 4; ni++)
#pragma unroll
            for (int j = 0; j < 2; j++) {
                int col = ncol0 + ni * 8 + 2 * t + j;
                hb[ni * 2 + j] = b1sm[col];
#pragma unroll
                for (int q = 0; q < 4; q++) w2r[q][ni * 2 + j] = W2sm[q * 64 + col];
            }
#pragma unroll
        for (int mi = 0; mi < 2; mi++)
#pragma unroll
            for (int half = 0; half < 2; half++) {
                int rrow = mrow0 + mi * 16 + half * 8 + g;
                float p[4] = {0.f, 0.f, 0.f, 0.f};
#pragma unroll
                for (int ni = 0; ni < 4; ni++)
#pragma unroll
                    for (int j = 0; j < 2; j++) {
                        float h = acc[mi][ni][half * 2 + j] + hb[ni * 2 + j];
                        h = fmaxf(h, 0.f);
#pragma unroll
                        for (int q = 0; q < 4; q++) p[q] += h * w2r[q][ni * 2 + j];
                    }
#pragma unroll
                for (int q = 0; q < 4; q++) {
                    p[q] += __shfl_xor_sync(0xffffffffu, p[q], 1);
                    p[q] += __shfl_xor_sync(0xffffffffu, p[q], 2);
                }
                if (t == 0) {
#pragma unroll
                    for (int q = 0; q < 4; q++)
                        atomicAdd(&qsm[(br * BM + rrow) * 4 + q], p[q]);
                }
            }
    }
    __syncthreads();

    // finalize: circuit expval via quadratic form + output affine
    {
        const int r = tid & 127, br = tid >> 7;
        float qv[4];
#pragma unroll
        for (int q = 0; q < 4; q++) qv[q] = qsm[(br * BM + r) * 4 + q];
        float cc[4], ss[4];
#pragma unroll
        for (int q = 0; q < 4; q++) sincosf(0.5f * qv[q], &ss[q], &cc[q]);
        float phi[16];
#pragma unroll
        for (int k = 0; k < 16; k++) {
            float v = (k & 8) ? ss[0] : cc[0];
            v *= (k & 4) ? ss[1] : cc[1];
            v *= (k & 2) ? ss[2] : cc[2];
            v *= (k & 1) ? ss[3] : cc[3];
            phi[k] = v;
        }
        const float* Am = Ash + br * 256;
        float e = 0.f;
#pragma unroll
        for (int j = 0; j < 16; j++) {
            float rs = 0.f;
#pragma unroll
            for (int i = 0; i < 16; i++) rs += Am[j * 16 + i] * phi[i];
            e += phi[j] * rs;
        }
        out[(size_t)br * B + m0 + r] = e + pbsh[br];
    }
}

// ---------------- launch ----------------
#define SMEM_FLOATS (BM * LDA + 2 * NCHUNK * LDA + 2 * BM * 4 + 2 * EPSZ + 512)
#define SMEM_BYTES  (SMEM_FLOATS * 4)

extern "C" void kernel_launch(void* const* d_in, const int* in_sizes, int n_in,
                              void* d_out, int out_size) {
    (void)n_in; (void)out_size;
    const float* state = (const float*)d_in[0];
    const float* action = (const float*)d_in[1];
    const float* q1_W1 = (const float*)d_in[2];
    const float* q1_b1 = (const float*)d_in[3];
    const float* q1_W2 = (const float*)d_in[4];
    const float* q1_b2 = (const float*)d_in[5];
    const float* q2_W1 = (const float*)d_in[6];
    const float* q2_b1 = (const float*)d_in[7];
    const float* q2_W2 = (const float*)d_in[8];
    const float* q2_b2 = (const float*)d_in[9];
    const float* q1_qw = (const float*)d_in[10];
    const float* q2_qw = (const float*)d_in[11];
    const float* q1_pw = (const float*)d_in[12];
    const float* q1_pb = (const float*)d_in[13];
    const float* q2_pw = (const float*)d_in[14];
    const float* q2_pb = (const float*)d_in[15];
    float* out = (float*)d_out;

    int B = in_sizes[0] / SD;

    cudaFuncSetAttribute(fused_kernel, cudaFuncAttributeMaxDynamicSharedMemorySize,
                         SMEM_BYTES);

    // W-pack blocks + 1 precompute block
    int prep_blocks = (2 * HDIM * KDIM + 255) / 256 + 1;
    prep_kernel<<<prep_blocks, 256>>>(q1_W1, q1_b1, q1_W2, q2_W1, q2_b1, q2_W2,
                                      q1_qw, q2_qw, q1_pw, q1_pb, q2_pw, q2_pb);
    fused_kernel<<<B / BM, 256, SMEM_BYTES>>>(state, action, q1_b2, q2_b2, out, B);
}